// round 13
// baseline (speedup 1.0000x reference)
#include <cuda_runtime.h>
#include <math.h>

#define B1n 4
#define B2n 1024
#define Rn  64
#define Tn  8192
#define Ln  256

// Each block handles (b1, two b2 samples). 256 threads = 64 l-threads x 4
// r-groups. Per r-iteration a thread issues 4 LDG.128 (both b2) back-to-back,
// then computes both lerps via the branch-free FSEL network. The two b2
// accumulator chains are independent -> compiler must keep both live, giving
// real MLP and halving exposed L1 latency per element.

__global__ void __launch_bounds__(Ln)
tof_predictor_kernel(const float* __restrict__ rec,        // (B1,R,T)
                     const float* __restrict__ samp,       // (B1,B2,3)
                     const float* __restrict__ emit,       // (3,)
                     const float* __restrict__ recv,       // (R,3)
                     float* __restrict__ out)              // (B1,B2)
{
    const int b2_0 = blockIdx.x * 2;           // handles b2_0 and b2_0+1
    const int b1   = blockIdx.y;
    const int tid  = threadIdx.x;

    __shared__ float2 s_pr[2][Rn];     // per b2: {frac, as_float(((r*Tn+i0a)<<2)|d)}
    __shared__ float  s_s1[2][4 * Ln];
    __shared__ float  s_s2[2][4 * Ln];
    __shared__ float  s_red[32];       // 8 warps x 4 values

    // ---- precompute per-(b2,receiver) base + frac (threads 0..127) ----
    const float fs_c = 96000.0f / 343.0f;
    if (tid < 2 * Rn) {
        const int b  = tid >> 6;       // which of the two b2
        const int r  = tid & 63;
        const float* sp = samp + ((size_t)b1 * B2n + b2_0 + b) * 3;
        float sx = sp[0], sy = sp[1], sz = sp[2];
        float ex = sx - emit[0], ey = sy - emit[1], ez = sz - emit[2];
        float d_e = sqrtf(ex * ex + ey * ey + ez * ez);
        const float* rp = recv + r * 3;
        float rx = sx - rp[0], ry = sy - rp[1], rz = sz - rp[2];
        float d_r = sqrtf(rx * rx + ry * ry + rz * rz);
        float start = (d_e + d_r) * fs_c;
        int i0 = (int)floorf(start);
        i0 = min(max(i0, 0), Tn - 2 - (Ln - 1) - 3);  // never fires in practice
        float frac = start - (float)i0;
        int i0a = i0 & ~3;
        int d   = i0 & 3;
        int packed = ((r * Tn + i0a) << 2) | d;
        s_pr[b][r] = make_float2(frac, __int_as_float(packed));
    }
    __syncthreads();

    const int g = tid >> 6;        // r-group 0..3 -> r = g*16 .. g*16+15
    const int t = tid & 63;        // l-thread     -> l = 4t .. 4t+3

    const float* recb = rec + (size_t)b1 * Rn * Tn + 4 * t;

    // accumulators: [b2] x {a0..a3, q0..q3}
    float a00 = 0.f, a01 = 0.f, a02 = 0.f, a03 = 0.f;
    float q00 = 0.f, q01 = 0.f, q02 = 0.f, q03 = 0.f;
    float a10 = 0.f, a11 = 0.f, a12 = 0.f, a13 = 0.f;
    float q10 = 0.f, q11 = 0.f, q12 = 0.f, q13 = 0.f;

    const int r_lo = g * 16;

#pragma unroll 4
    for (int k = 0; k < 16; ++k) {
        const int r = r_lo + k;
        float2 pr0 = s_pr[0][r];
        float2 pr1 = s_pr[1][r];
        int o0 = __float_as_int(pr0.y);
        int o1 = __float_as_int(pr1.y);

        // 4 independent LDG.128 issued back-to-back
        const float4* pA = (const float4*)(recb + (o0 >> 2));
        const float4* pB = (const float4*)(recb + (o1 >> 2));
        float4 A0 = __ldg(pA);
        float4 A1 = __ldg(pA + 1);
        float4 B0 = __ldg(pB);
        float4 B1 = __ldg(pB + 1);

        // ---- b2 #0 ----
        {
            float f = pr0.x;
            bool s2b = (o0 & 2) != 0;
            bool s1b = (o0 & 1) != 0;
            float v0 = A0.x, v1 = A0.y, v2 = A0.z, v3 = A0.w;
            float v4 = A1.x, v5 = A1.y, v6 = A1.z, v7 = A1.w;
            float u0 = s2b ? v2 : v0;
            float u1 = s2b ? v3 : v1;
            float u2 = s2b ? v4 : v2;
            float u3 = s2b ? v5 : v3;
            float u4 = s2b ? v6 : v4;
            float u5 = s2b ? v7 : v5;
            float w0 = s1b ? u1 : u0;
            float w1 = s1b ? u2 : u1;
            float w2 = s1b ? u3 : u2;
            float w3 = s1b ? u4 : u3;
            float w4 = s1b ? u5 : u4;
            float e0 = fmaf(f, w1 - w0, w0);
            float e1 = fmaf(f, w2 - w1, w1);
            float e2 = fmaf(f, w3 - w2, w2);
            float e3 = fmaf(f, w4 - w3, w3);
            a00 += e0; q00 = fmaf(e0, e0, q00);
            a01 += e1; q01 = fmaf(e1, e1, q01);
            a02 += e2; q02 = fmaf(e2, e2, q02);
            a03 += e3; q03 = fmaf(e3, e3, q03);
        }
        // ---- b2 #1 ----
        {
            float f = pr1.x;
            bool s2b = (o1 & 2) != 0;
            bool s1b = (o1 & 1) != 0;
            float v0 = B0.x, v1 = B0.y, v2 = B0.z, v3 = B0.w;
            float v4 = B1.x, v5 = B1.y, v6 = B1.z, v7 = B1.w;
            float u0 = s2b ? v2 : v0;
            float u1 = s2b ? v3 : v1;
            float u2 = s2b ? v4 : v2;
            float u3 = s2b ? v5 : v3;
            float u4 = s2b ? v6 : v4;
            float u5 = s2b ? v7 : v5;
            float w0 = s1b ? u1 : u0;
            float w1 = s1b ? u2 : u1;
            float w2 = s1b ? u3 : u2;
            float w3 = s1b ? u4 : u3;
            float w4 = s1b ? u5 : u4;
            float e0 = fmaf(f, w1 - w0, w0);
            float e1 = fmaf(f, w2 - w1, w1);
            float e2 = fmaf(f, w3 - w2, w2);
            float e3 = fmaf(f, w4 - w3, w3);
            a10 += e0; q10 = fmaf(e0, e0, q10);
            a11 += e1; q11 = fmaf(e1, e1, q11);
            a12 += e2; q12 = fmaf(e2, e2, q12);
            a13 += e3; q13 = fmaf(e3, e3, q13);
        }
    }

    // store per-group partials for both b2
    {
        float4* p;
        p = (float4*)&s_s1[0][g * Ln + 4 * t]; *p = make_float4(a00, a01, a02, a03);
        p = (float4*)&s_s2[0][g * Ln + 4 * t]; *p = make_float4(q00, q01, q02, q03);
        p = (float4*)&s_s1[1][g * Ln + 4 * t]; *p = make_float4(a10, a11, a12, a13);
        p = (float4*)&s_s2[1][g * Ln + 4 * t]; *p = make_float4(q10, q11, q12, q13);
    }
    __syncthreads();

    // combine across the 4 r-groups for both b2; thread tid owns l = tid
    float wl = 0.5f - 0.5f * cosf(3.14159265358979323846f * (float)tid * (1.0f / 255.0f));
    float wl2 = wl * wl;

    float num0, den0, num1, den1;
    {
        float S1 = s_s1[0][tid] + s_s1[0][Ln + tid] + s_s1[0][2 * Ln + tid] + s_s1[0][3 * Ln + tid];
        float S2 = s_s2[0][tid] + s_s2[0][Ln + tid] + s_s2[0][2 * Ln + tid] + s_s2[0][3 * Ln + tid];
        float sw1 = wl * S1, sw2 = wl2 * S2;
        num0 = sw2;
        den0 = (sw2 - sw1 * sw1 * (1.0f / (float)Rn)) * (1.0f / (float)(Rn - 1));
    }
    {
        float S1 = s_s1[1][tid] + s_s1[1][Ln + tid] + s_s1[1][2 * Ln + tid] + s_s1[1][3 * Ln + tid];
        float S2 = s_s2[1][tid] + s_s2[1][Ln + tid] + s_s2[1][2 * Ln + tid] + s_s2[1][3 * Ln + tid];
        float sw1 = wl * S1, sw2 = wl2 * S2;
        num1 = sw2;
        den1 = (sw2 - sw1 * sw1 * (1.0f / (float)Rn)) * (1.0f / (float)(Rn - 1));
    }

    // ---- block reduction of 4 values over 256 threads ----
    const unsigned FULL = 0xFFFFFFFFu;
#pragma unroll
    for (int off = 16; off > 0; off >>= 1) {
        num0 += __shfl_down_sync(FULL, num0, off);
        den0 += __shfl_down_sync(FULL, den0, off);
        num1 += __shfl_down_sync(FULL, num1, off);
        den1 += __shfl_down_sync(FULL, den1, off);
    }
    const int warp = tid >> 5;
    const int lane = tid & 31;
    if (lane == 0) {
        s_red[warp * 4 + 0] = num0;
        s_red[warp * 4 + 1] = den0;
        s_red[warp * 4 + 2] = num1;
        s_red[warp * 4 + 3] = den1;
    }
    __syncthreads();
    if (warp == 0) {
        // lanes 0..7 each hold one warp's 4 partials; reduce across 8 warps
        float n0 = (lane < 8) ? s_red[lane * 4 + 0] : 0.0f;
        float d0 = (lane < 8) ? s_red[lane * 4 + 1] : 0.0f;
        float n1 = (lane < 8) ? s_red[lane * 4 + 2] : 0.0f;
        float d1 = (lane < 8) ? s_red[lane * 4 + 3] : 0.0f;
#pragma unroll
        for (int off = 4; off > 0; off >>= 1) {
            n0 += __shfl_down_sync(FULL, n0, off);
            d0 += __shfl_down_sync(FULL, d0, off);
            n1 += __shfl_down_sync(FULL, n1, off);
            d1 += __shfl_down_sync(FULL, d1, off);
        }
        if (lane == 0) {
            float inv_rl = 1.0f / ((float)Rn * (float)Ln);
            float inv_l  = 1.0f / (float)Ln;
            out[(size_t)b1 * B2n + b2_0]     = (n0 * inv_rl) / (d0 * inv_l + 0.001f);
            out[(size_t)b1 * B2n + b2_0 + 1] = (n1 * inv_rl) / (d1 * inv_l + 0.001f);
        }
    }
}

extern "C" void kernel_launch(void* const* d_in, const int* in_sizes, int n_in,
                              void* d_out, int out_size)
{
    const float* recordings         = (const float*)d_in[0];
    const float* sample_locations   = (const float*)d_in[1];
    const float* emitter_location   = (const float*)d_in[2];
    const float* receiver_locations = (const float*)d_in[3];
    float* out = (float*)d_out;

    dim3 grid(B2n / 2, B1n);
    dim3 block(Ln);
    tof_predictor_kernel<<<grid, block>>>(recordings, sample_locations,
                                          emitter_location, receiver_locations, out);
}